// round 3
// baseline (speedup 1.0000x reference)
#include <cuda_runtime.h>
#include <stdint.h>

// Problem constants (fixed by the dataset):
//   x, y : (B=2, C=32, H=80, W=240) float32
//   out  : (B=2, 2C=64, D=64, H=80, W=240) float32
//   out[b, c,    d, h, w] = x[b, c,    h, w]       * (w >= d)   for c <  32
//   out[b, c,    d, h, w] = y[b, c-32, h, w - d]   * (w >= d)   for c >= 32
//
// Pure write-bandwidth-bound: 629 MB of stores vs 9.8 MB of (L2-resident) reads.

#define Bn 2
#define Cn 32
#define Dn 64
#define Hn 80
#define Wn 240
#define W4 (Wn / 4)   // 60 float4 per row

// block = (60, 4): tx = float4 index along W, ty = h sub-row
// grid  = (Hn/4, Dn, Bn * 2*Cn)
__global__ __launch_bounds__(240) void cost_volume_kernel(
    const float* __restrict__ x,
    const float* __restrict__ y,
    float* __restrict__ out)
{
    const int w4 = threadIdx.x;                 // 0..59
    const int h  = blockIdx.x * 4 + threadIdx.y; // 0..79
    const int d  = blockIdx.y;                  // 0..63
    const int bc = blockIdx.z;                  // 0..127  (b*64 + c2)
    const int b  = bc >> 6;
    const int c2 = bc & 63;                     // channel in [0,64)

    const int w = w4 * 4;

    float4 v;
    if (c2 < Cn) {
        // left: vector load from x, mask lanes where w+lane < d
        const float4* xr = reinterpret_cast<const float4*>(
            x + ((size_t)(b * Cn + c2) * Hn + h) * Wn);
        v = xr[w4];
        if (w     < d) v.x = 0.0f;
        if (w + 1 < d) v.y = 0.0f;
        if (w + 2 < d) v.z = 0.0f;
        if (w + 3 < d) v.w = 0.0f;
    } else {
        // right: shifted gather from y (coalesced, offset by -d), masked
        const float* yr = y + ((size_t)(b * Cn + (c2 - Cn)) * Hn + h) * Wn;
        v.x = (w     >= d) ? __ldg(yr + (w     - d)) : 0.0f;
        v.y = (w + 1 >= d) ? __ldg(yr + (w + 1 - d)) : 0.0f;
        v.z = (w + 2 >= d) ? __ldg(yr + (w + 2 - d)) : 0.0f;
        v.w = (w + 3 >= d) ? __ldg(yr + (w + 3 - d)) : 0.0f;
    }

    // out flat index in float4 units: (((bc*Dn + d)*Hn + h)*W4 + w4)
    float4* o = reinterpret_cast<float4*>(out);
    o[(((size_t)bc * Dn + d) * Hn + h) * W4 + w4] = v;
}

extern "C" void kernel_launch(void* const* d_in, const int* in_sizes, int n_in,
                              void* d_out, int out_size)
{
    const float* x = (const float*)d_in[0];
    const float* y = (const float*)d_in[1];
    float* out = (float*)d_out;

    dim3 block(W4, 4);                 // 240 threads
    dim3 grid(Hn / 4, Dn, Bn * 2 * Cn); // (20, 64, 128)
    cost_volume_kernel<<<grid, block>>>(x, y, out);
}

// round 4
// speedup vs baseline: 1.6545x; 1.6545x over previous
#include <cuda_runtime.h>
#include <stdint.h>

// x, y : (B=2, C=32, H=80, W=240) float32
// out  : (B=2, 64, 64, 80, 240) float32
//   out[b, c,    d, h, w] = x[b, c,    h, w]   * (w >= d)   c < 32
//   out[b, c,    d, h, w] = y[b, c-32, h, w-d] * (w >= d)   c >= 32
//
// One CTA = one (b, c, h) row; produces all 64 disparities for BOTH halves.
// 120 KB of stores per CTA, 16 STG.128 per thread. Write-bandwidth-bound.

#define Bn 2
#define Cn 32
#define Dn 64
#define Hn 80
#define Wn 240
#define W4 (Wn / 4)      // 60
#define HW (Hn * Wn)     // 19200

// block = (60, 8): tx = float4 index along W, ty = disparity group
// grid  = (Hn, Cn, Bn)
__global__ __launch_bounds__(480) void cost_volume_kernel(
    const float* __restrict__ x,
    const float* __restrict__ y,
    float* __restrict__ out)
{
    // y row de-interleaved: ysm[j][i] = y_row[i*4 + j].
    // Shifted reads y[idx] -> ysm[idx&3][idx>>2]: consecutive lanes hit
    // consecutive banks within one sub-array -> conflict-free.
    __shared__ float ysm[4][64];

    const int tx = threadIdx.x;   // 0..59  (w4)
    const int ty = threadIdx.y;   // 0..7   (d group)
    const int h  = blockIdx.x;
    const int c  = blockIdx.y;
    const int b  = blockIdx.z;

    const size_t row_in = ((size_t)(b * Cn + c) * Hn + h) * Wn;

    if (ty == 0) {
        float4 yv = reinterpret_cast<const float4*>(y + row_in)[tx];
        ysm[0][tx] = yv.x;
        ysm[1][tx] = yv.y;
        ysm[2][tx] = yv.z;
        ysm[3][tx] = yv.w;
    }
    const float4 xv = reinterpret_cast<const float4*>(x + row_in)[tx];
    __syncthreads();

    const int w = tx * 4;
    const size_t baseL = ((size_t)(b * 2 * Cn + c) * Dn * Hn + h) * (size_t)Wn + w;
    const size_t baseR = baseL + (size_t)Cn * Dn * HW;
    float* const outL = out + baseL;
    float* const outR = out + baseR;
    const int d0 = ty * 8;

#pragma unroll
    for (int k = 0; k < 8; ++k) {
        const int d = d0 + k;

        // left: masked copy of x
        float4 l = xv;
        if (w     < d) l.x = 0.0f;
        if (w + 1 < d) l.y = 0.0f;
        if (w + 2 < d) l.z = 0.0f;
        if (w + 3 < d) l.w = 0.0f;

        // right: shifted gather from de-interleaved smem
        float4 r;
        const int i0 = w - d;
        r.x = (i0     >= 0) ? ysm[ i0      & 3][(i0    ) >> 2] : 0.0f;
        r.y = (i0 + 1 >= 0) ? ysm[(i0 + 1) & 3][(i0 + 1) >> 2] : 0.0f;
        r.z = (i0 + 2 >= 0) ? ysm[(i0 + 2) & 3][(i0 + 2) >> 2] : 0.0f;
        r.w = (i0 + 3 >= 0) ? ysm[(i0 + 3) & 3][(i0 + 3) >> 2] : 0.0f;

        const size_t doff = (size_t)d * HW;
        __stcs(reinterpret_cast<float4*>(outL + doff), l);
        __stcs(reinterpret_cast<float4*>(outR + doff), r);
    }
}

extern "C" void kernel_launch(void* const* d_in, const int* in_sizes, int n_in,
                              void* d_out, int out_size)
{
    const float* x = (const float*)d_in[0];
    const float* y = (const float*)d_in[1];
    float* out = (float*)d_out;

    dim3 block(W4, 8);          // 480 threads = 15 full warps
    dim3 grid(Hn, Cn, Bn);      // 80 x 32 x 2 = 5120 CTAs
    cost_volume_kernel<<<grid, block>>>(x, y, out);
}

// round 6
// speedup vs baseline: 1.6880x; 1.0202x over previous
#include <cuda_runtime.h>
#include <stdint.h>

// x, y : (B=2, C=32, H=80, W=240) float32
// out  : (B=2, 64, 64, 80, 240) float32
//   out[b, c,    d, h, w] = x[b, c,    h, w]   * (w >= d)   c < 32
//   out[b, c,    d, h, w] = y[b, c-32, h, w-d] * (w >= d)   c >= 32
//
// One CTA = one (b, c, h) row; produces all 64 disparities for BOTH halves.
// Write-bandwidth-bound: 629 MB stores. Right-half gather uses a per-thread
// sliding window (windows for d and d+1 overlap by 3 elements) -> 11 LDS per
// thread instead of 32.

#define Bn 2
#define Cn 32
#define Dn 64
#define Hn 80
#define Wn 240
#define W4 (Wn / 4)      // 60
#define HW (Hn * Wn)     // 19200

// De-interleaved y row: ysm[j][i] = y_row[i*4 + j]. A gather at linear index
// idx maps to ysm[idx&3][idx>>2]; lane stride 4 in idx -> same j, consecutive
// i -> conflict-free banks.
#define YSM(idx) ysm[(idx) & 3][(idx) >> 2]

// block = (60, 8): tx = float4 index along W, ty = disparity group
// grid  = (Hn, Cn, Bn)
__global__ __launch_bounds__(480) void cost_volume_kernel(
    const float* __restrict__ x,
    const float* __restrict__ y,
    float* __restrict__ out)
{
    __shared__ float ysm[4][64];

    const int tx = threadIdx.x;   // 0..59  (w4)
    const int ty = threadIdx.y;   // 0..7   (d group)
    const int h  = blockIdx.x;
    const int c  = blockIdx.y;
    const int b  = blockIdx.z;

    const size_t row_in = ((size_t)(b * Cn + c) * Hn + h) * Wn;

    if (ty == 0) {
        float4 yv = reinterpret_cast<const float4*>(y + row_in)[tx];
        ysm[0][tx] = yv.x;
        ysm[1][tx] = yv.y;
        ysm[2][tx] = yv.z;
        ysm[3][tx] = yv.w;
    }
    const float4 xv = reinterpret_cast<const float4*>(x + row_in)[tx];
    __syncthreads();

    const int w  = tx * 4;
    const int d0 = ty * 8;

    const size_t baseL = ((size_t)(b * 2 * Cn + c) * Dn * Hn + h) * (size_t)Wn + w;
    float* outL = out + baseL + (size_t)d0 * HW;
    float* outR = outL + (size_t)Cn * Dn * HW;

    // Sliding window for the right half: for disparity d the window is
    // y[w-d .. w+3-d]. Initialize at d0, then each step shifts by one and
    // loads a single new element.
    const int i0 = w - d0;
    float r0 = (i0     >= 0) ? YSM(i0    ) : 0.0f;
    float r1 = (i0 + 1 >= 0) ? YSM(i0 + 1) : 0.0f;
    float r2 = (i0 + 2 >= 0) ? YSM(i0 + 2) : 0.0f;
    float r3 = (i0 + 3 >= 0) ? YSM(i0 + 3) : 0.0f;

#pragma unroll
    for (int k = 0; k < 8; ++k) {
        const int d = d0 + k;

        // left: masked copy of x
        float4 l = xv;
        if (w     < d) l.x = 0.0f;
        if (w + 1 < d) l.y = 0.0f;
        if (w + 2 < d) l.z = 0.0f;
        if (w + 3 < d) l.w = 0.0f;

        const float4 r = make_float4(r0, r1, r2, r3);

        __stcs(reinterpret_cast<float4*>(outL), l);
        __stcs(reinterpret_cast<float4*>(outR), r);
        outL += HW;
        outR += HW;

        // slide window for d+1
        const int ni = w - d - 1;
        r3 = r2; r2 = r1; r1 = r0;
        r0 = (ni >= 0) ? YSM(ni) : 0.0f;
    }
}

extern "C" void kernel_launch(void* const* d_in, const int* in_sizes, int n_in,
                              void* d_out, int out_size)
{
    const float* x = (const float*)d_in[0];
    const float* y = (const float*)d_in[1];
    float* out = (float*)d_out;

    dim3 block(W4, 8);          // 480 threads = 15 full warps
    dim3 grid(Hn, Cn, Bn);      // 80 x 32 x 2 = 5120 CTAs
    cost_volume_kernel<<<grid, block>>>(x, y, out);
}